// round 6
// baseline (speedup 1.0000x reference)
#include <cuda_runtime.h>
#include <cuda_bf16.h>

#define Mdim 2048
#define Ndim 4096
#define COLS 28          // columns of A owned per block
#define NB   147         // ceil(4096/28)
#define NT   256
#define NWARP 8
#define NREP 4           // y-replicas (RED contention divider)
#define OUTER_IT 100
#define INNER_IT 20
#define TOTAL_IT (OUTER_IT * INNER_IT + 1)   // 2001 rounds (epilogue folded)
#define RHO_C  1.0f
#define STEP_C 5e-5f
#define RPB 14           // rows owned per block for ybuf resets / outputs

// Global state (device globals: no allocation allowed)
__device__ __align__(16) float g_ybuf[3][NREP][Mdim]; // rotating replicated Ax accumulators
__device__ unsigned g_flags[NB];                      // barrier generation flags

__device__ __forceinline__ unsigned ldflag(const unsigned* p) {
    unsigned v;
    asm volatile("ld.global.cg.u32 %0, [%1];" : "=r"(v) : "l"(p));
    return v;
}

// Flag-array grid barrier: parallel arrival stores, warp-0-only sticky polling,
// wrap-safe generation compare, block released via __syncthreads.
__device__ __forceinline__ void gbar(unsigned gen) {
    __threadfence();
    __syncthreads();
    if (threadIdx.x == 0)
        asm volatile("st.global.cg.u32 [%0], %1;"
                     :: "l"(&g_flags[blockIdx.x]), "r"(gen) : "memory");
    if (threadIdx.x < 32) {
        unsigned pend = 0;
#pragma unroll
        for (int m = 0; m < 5; ++m)
            if ((int)threadIdx.x + 32 * m < NB) pend |= 1u << m;
        for (;;) {
#pragma unroll
            for (int m = 0; m < 5; ++m)
                if (pend & (1u << m)) {
                    unsigned v = ldflag(&g_flags[threadIdx.x + 32 * m]);
                    if ((int)(v - gen) >= 0) pend &= ~(1u << m);
                }
            if (__all_sync(0xffffffffu, pend == 0)) break;
        }
    }
    __syncthreads();
}

// Vector f32x4 reduction into global (sm_90+)
__device__ __forceinline__ void red4(float* p, float4 v) {
    asm volatile("red.global.add.v4.f32 [%0], {%1, %2, %3, %4};"
                 :: "l"(p), "f"(v.x), "f"(v.y), "f"(v.z), "f"(v.w) : "memory");
}

extern "C" __global__ void __launch_bounds__(NT, 1)
admm_persistent(const float* __restrict__ A,
                const float* __restrict__ b,
                const float* __restrict__ c,
                float* __restrict__ out)
{
    extern __shared__ float sm[];
    float* As  = sm;                      // COLS * Mdim floats, column-major A slice
    float* xs  = sm + COLS * Mdim;        // 32: x chunk
    float* cs  = xs + 32;                 // 32: c chunk
    float* red = cs + 32;                 // COLS * NWARP reduction scratch

    const int tid  = threadIdx.x;
    const int w    = tid >> 5;
    const int lane = tid & 31;
    const int bid  = blockIdx.x;
    const int j0   = bid * COLS;
    const int myCols = (Ndim - j0) < COLS ? (Ndim - j0) : COLS;
    const int g0 = w * 64 + lane;         // float4 row-group index (rows 4g0..4g0+3)
    const int g1 = g0 + 32;
    const int rep = bid & (NREP - 1);     // this block's RED replica

    // Generation base (monotonic across graph replays; all flags equal at entry)
    const unsigned base = ldflag(&g_flags[bid]);

    // ---- startup: load A column slice into SMEM (zero-padded) ----
    for (int idx = tid; idx < COLS * Mdim; idx += NT) {
        int i  = idx / COLS;
        int jj = idx - i * COLS;
        As[jj * Mdim + i] = (jj < myCols) ? A[(size_t)i * Ndim + (j0 + jj)] : 0.0f;
    }
    if (tid < 32) {
        xs[tid] = 0.0f;
        cs[tid] = (tid < myCols) ? c[j0 + tid] : 0.0f;
    }

    // Per-thread row state (replicated in every block): b, u, r for 8 rows
    float4 b0 = ((const float4*)b)[g0];
    float4 b1 = ((const float4*)b)[g1];
    float4 u0 = make_float4(0.f, 0.f, 0.f, 0.f);
    float4 u1 = make_float4(0.f, 0.f, 0.f, 0.f);
    float4 r0 = b0;                       // r = s + b - u = b initially
    float4 r1 = b1;

    // Row-owned ybuf zeroing (all 3 buffers x all replicas)
    const int rb = bid * RPB;
    int nrt = Mdim - rb;
    const int nr = nrt < 0 ? 0 : (nrt < RPB ? nrt : RPB);
    for (int ii = tid; ii < nr; ii += NT) {
#pragma unroll
        for (int bb = 0; bb < 3; ++bb)
#pragma unroll
            for (int rr = 0; rr < NREP; ++rr)
                __stcg(&g_ybuf[bb][rr][rb + ii], 0.0f);
    }
    gbar(base + 1u);

    const float4* As4 = (const float4*)As;   // index j*512 + g

    int bsel = 0, step = 0;
    for (int it = 0; it < TOTAL_IT; ++it) {
        // ---------------- phase A: partial Ax, RED into g_ybuf[bsel][rep] -------
        {
            float* yb = g_ybuf[bsel][rep];
            float xr[COLS];
#pragma unroll
            for (int j = 0; j < COLS; ++j) xr[j] = xs[j];
            float4 a0 = make_float4(0.f, 0.f, 0.f, 0.f);
#pragma unroll
            for (int j = 0; j < COLS; ++j) {
                float4 v0 = As4[j * 512 + g0];
                float xv = xr[j];
                a0.x = fmaf(v0.x, xv, a0.x);
                a0.y = fmaf(v0.y, xv, a0.y);
                a0.z = fmaf(v0.z, xv, a0.z);
                a0.w = fmaf(v0.w, xv, a0.w);
            }
            red4(&yb[4 * g0], a0);           // drains while g1 half computes
            float4 a1 = make_float4(0.f, 0.f, 0.f, 0.f);
#pragma unroll
            for (int j = 0; j < COLS; ++j) {
                float4 v1 = As4[j * 512 + g1];
                float xv = xr[j];
                a1.x = fmaf(v1.x, xv, a1.x);
                a1.y = fmaf(v1.y, xv, a1.y);
                a1.z = fmaf(v1.z, xv, a1.z);
                a1.w = fmaf(v1.w, xv, a1.w);
            }
            red4(&yb[4 * g1], a1);
        }
        gbar(base + 2u + (unsigned)it);      // the ONLY grid sync per iteration

        const int zsel = bsel >= 1 ? bsel - 1 : 2;    // (bsel+2)%3: reset target

        // ---- gather y: sum the NREP replicas (parallel L2 loads) ----
        float4 y0, y1;
        {
            float4 t00 = __ldcg((const float4*)g_ybuf[bsel][0] + g0);
            float4 t01 = __ldcg((const float4*)g_ybuf[bsel][1] + g0);
            float4 t02 = __ldcg((const float4*)g_ybuf[bsel][2] + g0);
            float4 t03 = __ldcg((const float4*)g_ybuf[bsel][3] + g0);
            float4 t10 = __ldcg((const float4*)g_ybuf[bsel][0] + g1);
            float4 t11 = __ldcg((const float4*)g_ybuf[bsel][1] + g1);
            float4 t12 = __ldcg((const float4*)g_ybuf[bsel][2] + g1);
            float4 t13 = __ldcg((const float4*)g_ybuf[bsel][3] + g1);
            y0.x = (t00.x + t01.x) + (t02.x + t03.x);
            y0.y = (t00.y + t01.y) + (t02.y + t03.y);
            y0.z = (t00.z + t01.z) + (t02.z + t03.z);
            y0.w = (t00.w + t01.w) + (t02.w + t03.w);
            y1.x = (t10.x + t11.x) + (t12.x + t13.x);
            y1.y = (t10.y + t11.y) + (t12.y + t13.y);
            y1.z = (t10.z + t11.z) + (t12.z + t13.z);
            y1.w = (t10.w + t11.w) + (t12.w + t13.w);
        }

        // ---- folded epilogue at outer boundaries (replicated, bit-identical) ---
        if (step == 0 && it > 0) {
            float4 sn0, sn1;
            sn0.x = fmaxf(y0.x - b0.x + u0.x, 0.0f);
            sn0.y = fmaxf(y0.y - b0.y + u0.y, 0.0f);
            sn0.z = fmaxf(y0.z - b0.z + u0.z, 0.0f);
            sn0.w = fmaxf(y0.w - b0.w + u0.w, 0.0f);
            sn1.x = fmaxf(y1.x - b1.x + u1.x, 0.0f);
            sn1.y = fmaxf(y1.y - b1.y + u1.y, 0.0f);
            sn1.z = fmaxf(y1.z - b1.z + u1.z, 0.0f);
            sn1.w = fmaxf(y1.w - b1.w + u1.w, 0.0f);
            u0.x += y0.x - sn0.x - b0.x;  u0.y += y0.y - sn0.y - b0.y;
            u0.z += y0.z - sn0.z - b0.z;  u0.w += y0.w - sn0.w - b0.w;
            u1.x += y1.x - sn1.x - b1.x;  u1.y += y1.y - sn1.y - b1.y;
            u1.z += y1.z - sn1.z - b1.z;  u1.w += y1.w - sn1.w - b1.w;
            r0.x = sn0.x + b0.x - u0.x;   r0.y = sn0.y + b0.y - u0.y;
            r0.z = sn0.z + b0.z - u0.z;   r0.w = sn0.w + b0.w - u0.w;
            r1.x = sn1.x + b1.x - u1.x;   r1.y = sn1.y + b1.y - u1.y;
            r1.z = sn1.z + b1.z - u1.z;   r1.w = sn1.w + b1.w - u1.w;

            if (it == TOTAL_IT - 1) {
                // ---- final outputs: s, u, lambda for owned rows; x block-local --
                const float* sv0 = (const float*)&sn0;
                const float* sv1 = (const float*)&sn1;
                const float* uv0 = (const float*)&u0;
                const float* uv1 = (const float*)&u1;
#pragma unroll
                for (int t = 0; t < 4; ++t) {
                    int row = 4 * g0 + t;
                    if (row >= rb && row < rb + nr) {
                        out[Ndim + row]            = sv0[t];
                        out[Ndim + Mdim + row]     = uv0[t];
                        out[Ndim + 2 * Mdim + row] = -RHO_C * uv0[t];
                    }
                    row = 4 * g1 + t;
                    if (row >= rb && row < rb + nr) {
                        out[Ndim + row]            = sv1[t];
                        out[Ndim + Mdim + row]     = uv1[t];
                        out[Ndim + 2 * Mdim + row] = -RHO_C * uv1[t];
                    }
                }
                if (tid < myCols) out[j0 + tid] = xs[tid];
                return;
            }
        }

        // ---------------- phase B: g = c + rho*A^T(y - r); x = max(x-step*g,0) --
        float4 e0 = make_float4(y0.x - r0.x, y0.y - r0.y, y0.z - r0.z, y0.w - r0.w);
        float4 e1 = make_float4(y1.x - r1.x, y1.y - r1.y, y1.z - r1.z, y1.w - r1.w);
        float acc[COLS];
#pragma unroll
        for (int j = 0; j < COLS; ++j) {
            float4 v0 = As4[j * 512 + g0];
            float4 v1 = As4[j * 512 + g1];
            float s = v0.x * e0.x;
            s = fmaf(v0.y, e0.y, s);
            s = fmaf(v0.z, e0.z, s);
            s = fmaf(v0.w, e0.w, s);
            s = fmaf(v1.x, e1.x, s);
            s = fmaf(v1.y, e1.y, s);
            s = fmaf(v1.z, e1.z, s);
            s = fmaf(v1.w, e1.w, s);
            acc[j] = s;
        }
#pragma unroll
        for (int j = 0; j < COLS; ++j) {
            float v = acc[j];
            v += __shfl_xor_sync(0xffffffffu, v, 16);
            v += __shfl_xor_sync(0xffffffffu, v, 8);
            v += __shfl_xor_sync(0xffffffffu, v, 4);
            v += __shfl_xor_sync(0xffffffffu, v, 2);
            v += __shfl_xor_sync(0xffffffffu, v, 1);
            if (lane == 0) red[j * NWARP + w] = v;
        }
        // reset the buffer accumulated 2 iterations from now (safe: post-barrier)
        for (int ii = tid; ii < nr; ii += NT) {
#pragma unroll
            for (int rr = 0; rr < NREP; ++rr)
                __stcg(&g_ybuf[zsel][rr][rb + ii], 0.0f);
        }
        __syncthreads();
        if (tid < COLS) {
            float g = 0.0f;
#pragma unroll
            for (int ww = 0; ww < NWARP; ++ww) g += red[tid * NWARP + ww];
            float xn = xs[tid] - STEP_C * (cs[tid] + RHO_C * g);
            xs[tid] = fmaxf(xn, 0.0f);
        }
        __syncthreads();

        step = (step + 1 == INNER_IT) ? 0 : step + 1;
        bsel = (bsel + 1 == 3) ? 0 : bsel + 1;
    }
}

extern "C" void kernel_launch(void* const* d_in, const int* in_sizes, int n_in,
                              void* d_out, int out_size) {
    const float* A = nullptr;
    const float* b = nullptr;
    const float* c = nullptr;
    for (int k = 0; k < n_in; ++k) {
        if (in_sizes[k] == Mdim * Ndim)      A = (const float*)d_in[k];
        else if (in_sizes[k] == Mdim)        b = (const float*)d_in[k];
        else if (in_sizes[k] == Ndim)        c = (const float*)d_in[k];
    }
    float* out = (float*)d_out;
    size_t shmem = (size_t)(COLS * Mdim + 32 + 32 + COLS * NWARP) * sizeof(float);
    cudaFuncSetAttribute(admm_persistent,
                         cudaFuncAttributeMaxDynamicSharedMemorySize, (int)shmem);
    admm_persistent<<<NB, NT, shmem>>>(A, b, c, out);
}

// round 11
// speedup vs baseline: 1.3569x; 1.3569x over previous
#include <cuda_runtime.h>
#include <cuda_bf16.h>

#define Mdim 2048
#define Ndim 4096
#define COLS 28          // columns of A owned per block
#define NB   147         // ceil(4096/28)
#define NT   256
#define NWARP 8
#define OUTER_IT 100
#define INNER_IT 20
#define TOTAL_IT (OUTER_IT * (INNER_IT + 1))
#define RHO_C  1.0f
#define STEP_C 5e-5f
#define RPB 14           // rows owned per block (resets/epilogue): 147*14 >= 2048

// Global state (device globals: no allocation allowed)
__device__ __align__(16) float g_ybuf[3][Mdim];   // rotating Ax accumulators
__device__ __align__(16) float g_r[Mdim];         // r = s + b - u
__device__ float g_u[Mdim];
__device__ unsigned g_flags[NB];                  // barrier generation flags

__device__ __forceinline__ unsigned ldflag(const unsigned* p) {
    unsigned v;
    asm volatile("ld.global.cg.u32 %0, [%1];" : "=r"(v) : "l"(p));
    return v;
}

// Flag-array grid barrier: parallel arrival stores, warp-0-only sticky polling,
// wrap-safe generation compare, block released via __syncthreads. (Round-3 proven.)
__device__ __forceinline__ void gbar(unsigned gen) {
    __threadfence();
    __syncthreads();
    if (threadIdx.x == 0)
        asm volatile("st.global.cg.u32 [%0], %1;"
                     :: "l"(&g_flags[blockIdx.x]), "r"(gen) : "memory");
    if (threadIdx.x < 32) {
        unsigned pend = 0;
#pragma unroll
        for (int m = 0; m < 5; ++m)
            if ((int)threadIdx.x + 32 * m < NB) pend |= 1u << m;
        for (;;) {
#pragma unroll
            for (int m = 0; m < 5; ++m)
                if (pend & (1u << m)) {
                    unsigned v = ldflag(&g_flags[threadIdx.x + 32 * m]);
                    if ((int)(v - gen) >= 0) pend &= ~(1u << m);
                }
            if (__all_sync(0xffffffffu, pend == 0)) break;
        }
    }
    __syncthreads();
}

// Vector f32x4 reduction into global (sm_90+)
__device__ __forceinline__ void red4(float* p, float4 v) {
    asm volatile("red.global.add.v4.f32 [%0], {%1, %2, %3, %4};"
                 :: "l"(p), "f"(v.x), "f"(v.y), "f"(v.z), "f"(v.w) : "memory");
}

extern "C" __global__ void __launch_bounds__(NT, 1)
admm_persistent(const float* __restrict__ A,
                const float* __restrict__ b,
                const float* __restrict__ c,
                float* __restrict__ out)
{
    extern __shared__ float sm[];
    float* As  = sm;                      // COLS * Mdim floats, column-major A slice
    float* xs  = sm + COLS * Mdim;        // 32: x chunk
    float* cs  = xs + 32;                 // 32: c chunk
    float* red = cs + 32;                 // COLS * 16 reduction scratch (2 partials/warp)

    const int tid  = threadIdx.x;
    const int w    = tid >> 5;
    const int lane = tid & 31;
    const int bid  = blockIdx.x;
    const int j0   = bid * COLS;
    const int myCols = (Ndim - j0) < COLS ? (Ndim - j0) : COLS;
    const int g0 = w * 64 + lane;         // float4 row-group index (rows 4g0..4g0+3)
    const int g1 = g0 + 32;

    // Generation base (monotonic across graph replays; all flags equal at entry)
    const unsigned base = ldflag(&g_flags[bid]);

    // ---- startup: load A column slice into SMEM (zero-padded), init state ----
    for (int idx = tid; idx < COLS * Mdim; idx += NT) {
        int i  = idx / COLS;
        int jj = idx - i * COLS;
        As[jj * Mdim + i] = (jj < myCols) ? A[(size_t)i * Ndim + (j0 + jj)] : 0.0f;
    }
    if (tid < 32) {
        xs[tid] = 0.0f;
        cs[tid] = (tid < myCols) ? c[j0 + tid] : 0.0f;
    }
    const int rb = bid * RPB;
    int nrt = Mdim - rb;
    const int nr = nrt < 0 ? 0 : (nrt < RPB ? nrt : RPB);
    for (int ii = tid; ii < nr; ii += NT) {
        int i = rb + ii;
        float bv = b[i];
        g_u[i] = 0.0f;
        g_r[i] = bv;                     // r = s + b - u = b initially
        __stcg(&g_ybuf[0][i], 0.0f);
        __stcg(&g_ybuf[1][i], 0.0f);
        __stcg(&g_ybuf[2][i], 0.0f);
    }
    gbar(base + 1u);

    const float4* As4 = (const float4*)As;   // index j*512 + g

    // Register-cached r (reloaded at each outer's first inner step)
    float4 r0 = make_float4(0.f, 0.f, 0.f, 0.f);
    float4 r1 = make_float4(0.f, 0.f, 0.f, 0.f);

    int bsel = 0, step = 0;
    for (int it = 0; it < TOTAL_IT; ++it) {
        // ---------------- phase A: partial Ax, RED into g_ybuf[bsel] ------------
        {
            float* yb = g_ybuf[bsel];
            float xr[COLS];
#pragma unroll
            for (int j = 0; j < COLS; ++j) xr[j] = xs[j];
            float4 a0 = make_float4(0.f, 0.f, 0.f, 0.f);
#pragma unroll
            for (int j = 0; j < COLS; ++j) {
                float4 v0 = As4[j * 512 + g0];
                float xv = xr[j];
                a0.x = fmaf(v0.x, xv, a0.x);
                a0.y = fmaf(v0.y, xv, a0.y);
                a0.z = fmaf(v0.z, xv, a0.z);
                a0.w = fmaf(v0.w, xv, a0.w);
            }
            red4(&yb[4 * g0], a0);           // drains while g1 half computes
            float4 a1 = make_float4(0.f, 0.f, 0.f, 0.f);
#pragma unroll
            for (int j = 0; j < COLS; ++j) {
                float4 v1 = As4[j * 512 + g1];
                float xv = xr[j];
                a1.x = fmaf(v1.x, xv, a1.x);
                a1.y = fmaf(v1.y, xv, a1.y);
                a1.z = fmaf(v1.z, xv, a1.z);
                a1.w = fmaf(v1.w, xv, a1.w);
            }
            red4(&yb[4 * g1], a1);
        }
        gbar(base + 2u + (unsigned)it);      // the ONLY grid sync per iteration

        const float* yb = g_ybuf[bsel];
        float* zb = g_ybuf[bsel >= 1 ? bsel - 1 : 2];   // (bsel+2)%3: reset target

        if (step < INNER_IT) {
            // ------------- phase B: g = c + rho*A^T(Ax - r); x = max(x-step*g,0)
            if (step == 0) {                 // r constant within an outer iteration
                r0 = __ldcg((const float4*)g_r + g0);
                r1 = __ldcg((const float4*)g_r + g1);
            }
            float4 y0 = __ldcg((const float4*)yb + g0);
            float4 y1 = __ldcg((const float4*)yb + g1);
            float4 e0 = make_float4(y0.x - r0.x, y0.y - r0.y, y0.z - r0.z, y0.w - r0.w);
            float4 e1 = make_float4(y1.x - r1.x, y1.y - r1.y, y1.z - r1.z, y1.w - r1.w);
            float acc[COLS];
#pragma unroll
            for (int j = 0; j < COLS; ++j) {
                float4 v0 = As4[j * 512 + g0];
                float4 v1 = As4[j * 512 + g1];
                float s = v0.x * e0.x;
                s = fmaf(v0.y, e0.y, s);
                s = fmaf(v0.z, e0.z, s);
                s = fmaf(v0.w, e0.w, s);
                s = fmaf(v1.x, e1.x, s);
                s = fmaf(v1.y, e1.y, s);
                s = fmaf(v1.z, e1.z, s);
                s = fmaf(v1.w, e1.w, s);
                acc[j] = s;
            }
            // 4-round butterfly: 2 partials per warp per column
#pragma unroll
            for (int j = 0; j < COLS; ++j) {
                float v = acc[j];
                v += __shfl_xor_sync(0xffffffffu, v, 16);
                v += __shfl_xor_sync(0xffffffffu, v, 8);
                v += __shfl_xor_sync(0xffffffffu, v, 4);
                v += __shfl_xor_sync(0xffffffffu, v, 2);
                if (lane < 2) red[j * 16 + w * 2 + lane] = v;
            }
            // reset the buffer accumulated 2 iterations from now (safe: post-barrier)
            for (int ii = tid; ii < nr; ii += NT) __stcg(&zb[rb + ii], 0.0f);
            __syncthreads();
            if (tid < COLS) {
                float g = 0.0f;
#pragma unroll
                for (int k = 0; k < 16; ++k) g += red[tid * 16 + k];
                float xn = xs[tid] - STEP_C * (cs[tid] + RHO_C * g);
                xs[tid] = fmaxf(xn, 0.0f);
            }
            __syncthreads();
            ++step;
        } else {
            // ------------- epilogue: s, u, r updates (row-owned) ---------------
            for (int ii = tid; ii < nr; ii += NT) {
                int i = rb + ii;
                float Ax = __ldcg(&yb[i]);
                float bi = b[i];
                float ui = g_u[i];
                float sn = fmaxf(Ax - bi + ui, 0.0f);
                float un = ui + (Ax - sn - bi);
                g_u[i] = un;
                g_r[i] = sn + bi - un;           // r = s + b - u
                __stcg(&zb[i], 0.0f);
                if (it == TOTAL_IT - 1) {
                    out[Ndim + i]            = sn;          // s
                    out[Ndim + Mdim + i]     = un;          // u
                    out[Ndim + 2 * Mdim + i] = -RHO_C * un; // lambda_kkt
                }
            }
            step = 0;
        }
        bsel = (bsel + 1 == 3) ? 0 : bsel + 1;
    }

    // final x (block-local)
    if (tid < myCols) out[j0 + tid] = xs[tid];
}

extern "C" void kernel_launch(void* const* d_in, const int* in_sizes, int n_in,
                              void* d_out, int out_size) {
    const float* A = nullptr;
    const float* b = nullptr;
    const float* c = nullptr;
    for (int k = 0; k < n_in; ++k) {
        if (in_sizes[k] == Mdim * Ndim)      A = (const float*)d_in[k];
        else if (in_sizes[k] == Mdim)        b = (const float*)d_in[k];
        else if (in_sizes[k] == Ndim)        c = (const float*)d_in[k];
    }
    float* out = (float*)d_out;
    size_t shmem = (size_t)(COLS * Mdim + 32 + 32 + COLS * 16) * sizeof(float); // 231,424 B
    cudaFuncSetAttribute(admm_persistent,
                         cudaFuncAttributeMaxDynamicSharedMemorySize, (int)shmem);
    admm_persistent<<<NB, NT, shmem>>>(A, b, c, out);
}